// round 2
// baseline (speedup 1.0000x reference)
#include <cuda_runtime.h>

// Problem constants (fixed by the reference setup_inputs)
#define S_LEN   16384   // s
#define T_ROWS  8192    // t
#define BATCH   16      // b
#define NH      16      // top-k
#define THREADS 256
#define CAP     1024    // candidate buffer per metric

typedef unsigned long long u64;
typedef unsigned int u32;

// Output layout: flattened tuple in reference order, all float32
//   x_nearest [16, 8192, 16, 1]  -> 2,097,152
//   indices_dist [8192, 16]      ->   131,072
//   indices_dlon [8192, 16]
//   indices_dlat [8192, 16]
#define OFF_XN    0
#define OFF_IDIST (BATCH * T_ROWS * NH)
#define OFF_ILON  (OFF_IDIST + T_ROWS * NH)
#define OFF_ILAT  (OFF_ILON + T_ROWS * NH)

__global__ __launch_bounds__(THREADS) void nn_topk_kernel(
    const float* __restrict__ x,
    const float* __restrict__ dlon,
    const float* __restrict__ dlat,
    float* __restrict__ out)
{
    // sbuf doubles as: 3 candidate buffers of CAP (3072 used) in the fast path,
    // and a 4096-entry (THREADS*NH) dump area in the exact fallback path.
    __shared__ u64 sbuf[THREADS * NH];
    __shared__ int scnt[3];
    __shared__ u64 sres[3][NH];
    __shared__ u64 sbest;

    const int tid = threadIdx.x;
    const int t   = blockIdx.x;

    if (tid < 3) scnt[tid] = 0;
    __syncthreads();

    const float4* lon4 = reinterpret_cast<const float4*>(dlon + (size_t)t * S_LEN);
    const float4* lat4 = reinterpret_cast<const float4*>(dlat + (size_t)t * S_LEN);

    // Quantile-~64/16384 thresholds for N(0,1) inputs (bit-pattern compares).
    // Fallback below guarantees correctness if the distribution assumption breaks.
    const u32 TH_ABS = __float_as_uint(0.0050f);  // |lon|, |lat|
    const u32 TH_D2  = __float_as_uint(0.0080f);  // lon^2 + lat^2

    for (int i = tid; i < S_LEN / 4; i += THREADS) {
        float4 lo = __ldcs(&lon4[i]);
        float4 la = __ldcs(&lat4[i]);
        float lof[4] = {lo.x, lo.y, lo.z, lo.w};
        float laf[4] = {la.x, la.y, la.z, la.w};
        const int base = i << 2;
#pragma unroll
        for (int j = 0; j < 4; ++j) {
            const u32 abl = __float_as_uint(lof[j]) & 0x7fffffffu;
            const u32 aba = __float_as_uint(laf[j]) & 0x7fffffffu;
            const float d2 = fmaf(lof[j], lof[j], laf[j] * laf[j]);
            const u32 d2b = __float_as_uint(d2);
            const u32 idx = (u32)(base + j);
            if (d2b < TH_D2) {
                int p = atomicAdd(&scnt[0], 1);
                if (p < CAP) sbuf[0 * CAP + p] = ((u64)d2b << 14) | idx;
            }
            if (abl < TH_ABS) {
                int p = atomicAdd(&scnt[1], 1);
                if (p < CAP) sbuf[1 * CAP + p] = ((u64)abl << 14) | idx;
            }
            if (aba < TH_ABS) {
                int p = atomicAdd(&scnt[2], 1);
                if (p < CAP) sbuf[2 * CAP + p] = ((u64)aba << 14) | idx;
            }
        }
    }
    __syncthreads();

    bool need_fb[3];
#pragma unroll
    for (int m = 0; m < 3; ++m)
        need_fb[m] = (scnt[m] < NH) || (scnt[m] > CAP);

    const int wid  = tid >> 5;
    const int lane = tid & 31;

    // Fast path: warp m extracts the 16 smallest packed keys for metric m.
    if (wid < 3 && !need_fb[wid]) {
        const int m = wid;
        const int n = scnt[m];
        for (int r = 0; r < NH; ++r) {
            u64 best = ~0ull;
            for (int p = lane; p < n; p += 32) {
                u64 k = sbuf[m * CAP + p];
                u64 cand = (k << 10) | (u64)p;  // key(<=46b) << 10 | pos(<=10b)
                if (cand < best) best = cand;
            }
#pragma unroll
            for (int o = 16; o > 0; o >>= 1) {
                u64 other = __shfl_down_sync(0xffffffffu, best, o);
                if (other < best) best = other;
            }
            best = __shfl_sync(0xffffffffu, best, 0);
            if (lane == 0) {
                sres[m][r] = best >> 10;
                sbuf[m * CAP + (int)(best & 1023ull)] = ~0ull;
            }
            __syncwarp();
        }
    }
    __syncthreads();

    // Exact fallback (guaranteed correct; probability of execution ~0):
    // whole block recomputes metric m from global, per-thread top-16 insertion,
    // then 16 rounds of block-wide atomicMin extraction.
    for (int m = 0; m < 3; ++m) {
        if (!need_fb[m]) continue;
        u64 loc[NH];
#pragma unroll
        for (int k = 0; k < NH; ++k) loc[k] = ~0ull;
        const float* a  = dlon + (size_t)t * S_LEN;
        const float* b2 = dlat + (size_t)t * S_LEN;
        for (int i = tid; i < S_LEN; i += THREADS) {
            const float lo = a[i];
            const float la = b2[i];
            u32 bits;
            if (m == 0)      bits = __float_as_uint(fmaf(lo, lo, la * la));
            else if (m == 1) bits = __float_as_uint(lo) & 0x7fffffffu;
            else             bits = __float_as_uint(la) & 0x7fffffffu;
            u64 key = ((u64)bits << 14) | (u32)i;
            if (key < loc[NH - 1]) {
                loc[NH - 1] = key;
#pragma unroll
                for (int k = NH - 1; k > 0; --k) {
                    if (loc[k] < loc[k - 1]) { u64 tmp = loc[k]; loc[k] = loc[k - 1]; loc[k - 1] = tmp; }
                }
            }
        }
        __syncthreads();
#pragma unroll
        for (int k = 0; k < NH; ++k) sbuf[tid * NH + k] = loc[k];
        __syncthreads();
        for (int r = 0; r < NH; ++r) {
            if (tid == 0) sbest = ~0ull;
            __syncthreads();
            u64 mymin = ~0ull;
#pragma unroll
            for (int k = 0; k < NH; ++k) mymin = min(mymin, sbuf[tid * NH + k]);
            atomicMin(&sbest, mymin);
            __syncthreads();
            const u64 bb = sbest;
            if (tid == 0) sres[m][r] = bb;
#pragma unroll
            for (int k = 0; k < NH; ++k)
                if (sbuf[tid * NH + k] == bb) sbuf[tid * NH + k] = ~0ull;
            __syncthreads();
        }
    }
    __syncthreads();

    // Emit index outputs (as float32)
    if (tid < NH) {
        const int j = tid;
        out[OFF_IDIST + t * NH + j] = (float)(u32)(sres[0][j] & 0x3fffull);
        out[OFF_ILON  + t * NH + j] = (float)(u32)(sres[1][j] & 0x3fffull);
        out[OFF_ILAT  + t * NH + j] = (float)(u32)(sres[2][j] & 0x3fffull);
    }

    // Gather x_nearest: tid = b*NH + j  (BATCH*NH == THREADS)
    {
        const int b = tid >> 4;
        const int j = tid & 15;
        const int idx = (int)(sres[0][j] & 0x3fffull);
        out[OFF_XN + (size_t)b * (T_ROWS * NH) + (size_t)t * NH + j] =
            __ldg(&x[b * S_LEN + idx]);
    }
}

extern "C" void kernel_launch(void* const* d_in, const int* in_sizes, int n_in,
                              void* d_out, int out_size) {
    const float* x    = (const float*)d_in[0];
    const float* dlon = (const float*)d_in[1];
    const float* dlat = (const float*)d_in[2];
    float* out        = (float*)d_out;
    nn_topk_kernel<<<T_ROWS, THREADS>>>(x, dlon, dlat, out);
}

// round 6
// speedup vs baseline: 1.2666x; 1.2666x over previous
#include <cuda_runtime.h>

// Problem constants (fixed by the reference setup_inputs)
#define S_LEN   16384   // s
#define T_ROWS  8192    // t
#define BATCH   16      // b
#define NH      16      // top-k
#define THREADS 256
#define CAP     512     // candidate buffer per metric (expected ~65 hits)

typedef unsigned long long u64;
typedef unsigned int u32;

// Output layout: flattened tuple in reference order, all float32
#define OFF_XN    0
#define OFF_IDIST (BATCH * T_ROWS * NH)
#define OFF_ILON  (OFF_IDIST + T_ROWS * NH)
#define OFF_ILAT  (OFF_ILON + T_ROWS * NH)

__global__ __launch_bounds__(THREADS, 8) void nn_topk_kernel(
    const float* __restrict__ x,
    const float* __restrict__ dlon,
    const float* __restrict__ dlat,
    float* __restrict__ out)
{
    __shared__ u64 sbuf[3 * CAP];     // 12 KB candidate buffers
    __shared__ int scnt[3];
    __shared__ u64 sres[3][NH];
    __shared__ u64 sbest;

    const int tid = threadIdx.x;
    const int t   = blockIdx.x;

    if (tid < 3) scnt[tid] = 0;
    __syncthreads();

    const float4* lon4 = reinterpret_cast<const float4*>(dlon + (size_t)t * S_LEN);
    const float4* lat4 = reinterpret_cast<const float4*>(dlat + (size_t)t * S_LEN);

    // ~64/16384-quantile thresholds for N(0,1) inputs (bit-pattern compares).
    // Exact fallback below guarantees correctness regardless.
    const u32 TH_ABS = __float_as_uint(0.0050f);  // |lon|, |lat|
    const u32 TH_D2  = __float_as_uint(0.0080f);  // lon^2 + lat^2

    for (int i = tid; i < S_LEN / 4; i += THREADS) {
        float4 lo = __ldcs(&lon4[i]);
        float4 la = __ldcs(&lat4[i]);
        float lof[4] = {lo.x, lo.y, lo.z, lo.w};
        float laf[4] = {la.x, la.y, la.z, la.w};
        u32 abl[4], aba[4], d2b[4];
        u32 hit = 0;
#pragma unroll
        for (int j = 0; j < 4; ++j) {
            abl[j] = __float_as_uint(lof[j]) & 0x7fffffffu;
            aba[j] = __float_as_uint(laf[j]) & 0x7fffffffu;
            d2b[j] = __float_as_uint(fmaf(lof[j], lof[j], laf[j] * laf[j]));
            if (d2b[j] < TH_D2 || abl[j] < TH_ABS || aba[j] < TH_ABS) hit |= (1u << j);
        }
        if (hit) {  // rare: ~3*65 hits per 16384 elements per row
            const int base = i << 2;
#pragma unroll
            for (int j = 0; j < 4; ++j) {
                if (!(hit & (1u << j))) continue;
                const u32 idx = (u32)(base + j);
                if (d2b[j] < TH_D2) {
                    int p = atomicAdd(&scnt[0], 1);
                    if (p < CAP) sbuf[0 * CAP + p] = ((u64)d2b[j] << 14) | idx;
                }
                if (abl[j] < TH_ABS) {
                    int p = atomicAdd(&scnt[1], 1);
                    if (p < CAP) sbuf[1 * CAP + p] = ((u64)abl[j] << 14) | idx;
                }
                if (aba[j] < TH_ABS) {
                    int p = atomicAdd(&scnt[2], 1);
                    if (p < CAP) sbuf[2 * CAP + p] = ((u64)aba[j] << 14) | idx;
                }
            }
        }
    }
    __syncthreads();

    bool need_fb[3];
#pragma unroll
    for (int m = 0; m < 3; ++m)
        need_fb[m] = (scnt[m] < NH) || (scnt[m] > CAP);

    const int wid  = tid >> 5;
    const int lane = tid & 31;

    // Fast path: warp m extracts the 16 smallest packed keys for metric m.
    // Key = valuebits<<14 | element_index, so ties break by ascending index
    // exactly like jax.lax.top_k on negated values.
    if (wid < 3 && !need_fb[wid]) {
        const int m = wid;
        const int n = scnt[m];
        for (int r = 0; r < NH; ++r) {
            u64 best = ~0ull;
            for (int p = lane; p < n; p += 32) {
                u64 k = sbuf[m * CAP + p];
                u64 cand = (k << 10) | (u64)p;  // key(46b) << 10 | pos(<=9b)
                if (cand < best) best = cand;
            }
#pragma unroll
            for (int o = 16; o > 0; o >>= 1) {
                u64 other = __shfl_down_sync(0xffffffffu, best, o);
                if (other < best) best = other;
            }
            best = __shfl_sync(0xffffffffu, best, 0);
            if (lane == 0) {
                sres[m][r] = best >> 10;
                sbuf[m * CAP + (int)(best & 1023ull)] = ~0ull;
            }
            __syncwarp();
        }
    }
    __syncthreads();

    // Exact fallback (guaranteed correct; probability ~0 of execution).
    // Register/local-resident per-thread top-16, then 16 rounds of
    // block-wide atomicMin extraction. No shared dump buffer needed.
    for (int m = 0; m < 3; ++m) {
        if (!need_fb[m]) continue;
        u64 loc[NH];
#pragma unroll
        for (int k = 0; k < NH; ++k) loc[k] = ~0ull;
        const float* a  = dlon + (size_t)t * S_LEN;
        const float* b2 = dlat + (size_t)t * S_LEN;
        for (int i = tid; i < S_LEN; i += THREADS) {
            const float lo = a[i];
            const float la = b2[i];
            u32 bits;
            if (m == 0)      bits = __float_as_uint(fmaf(lo, lo, la * la));
            else if (m == 1) bits = __float_as_uint(lo) & 0x7fffffffu;
            else             bits = __float_as_uint(la) & 0x7fffffffu;
            u64 key = ((u64)bits << 14) | (u32)i;
            if (key < loc[NH - 1]) {
                loc[NH - 1] = key;
#pragma unroll
                for (int k = NH - 1; k > 0; --k) {
                    if (loc[k] < loc[k - 1]) { u64 tmp = loc[k]; loc[k] = loc[k - 1]; loc[k - 1] = tmp; }
                }
            }
        }
        __syncthreads();
        for (int r = 0; r < NH; ++r) {
            if (tid == 0) sbest = ~0ull;
            __syncthreads();
            u64 mymin = ~0ull;
#pragma unroll
            for (int k = 0; k < NH; ++k) mymin = min(mymin, loc[k]);
            atomicMin(&sbest, mymin);
            __syncthreads();
            const u64 bb = sbest;
            if (tid == 0) sres[m][r] = bb;
#pragma unroll
            for (int k = 0; k < NH; ++k)
                if (loc[k] == bb) loc[k] = ~0ull;   // keys unique (contain index)
            __syncthreads();
        }
    }
    __syncthreads();

    // Emit index outputs (as float32)
    if (tid < NH) {
        const int j = tid;
        out[OFF_IDIST + t * NH + j] = (float)(u32)(sres[0][j] & 0x3fffull);
        out[OFF_ILON  + t * NH + j] = (float)(u32)(sres[1][j] & 0x3fffull);
        out[OFF_ILAT  + t * NH + j] = (float)(u32)(sres[2][j] & 0x3fffull);
    }

    // Gather x_nearest: tid = b*NH + j  (BATCH*NH == THREADS)
    {
        const int b = tid >> 4;
        const int j = tid & 15;
        const int idx = (int)(sres[0][j] & 0x3fffull);
        out[OFF_XN + (size_t)b * (T_ROWS * NH) + (size_t)t * NH + j] =
            __ldg(&x[b * S_LEN + idx]);
    }
}

extern "C" void kernel_launch(void* const* d_in, const int* in_sizes, int n_in,
                              void* d_out, int out_size) {
    const float* x    = (const float*)d_in[0];
    const float* dlon = (const float*)d_in[1];
    const float* dlat = (const float*)d_in[2];
    float* out        = (float*)d_out;
    nn_topk_kernel<<<T_ROWS, THREADS>>>(x, dlon, dlat, out);
}